// round 1
// baseline (speedup 1.0000x reference)
#include <cuda_runtime.h>
#include <cstdint>

#define N_TOK   32768
#define K_CODES 1024
#define D_DIM   256
#define BM 64
#define BN 64

// Output layout: reference tuple concatenated as float32 in return order.
#define OFF_ZQ    0ull
#define OFF_CODES 8388608ull
#define OFF_LOSS  8421376ull
#define OFF_PERP  8421377ull
#define OFF_ENT   8421378ull
#define OFF_SA    8421379ull
#define OFF_EMBED 41975811ull
#define OFF_CS    42237955ull
#define OFF_EA    42238979ull

// Scratch (allowed: __device__ globals, no runtime allocation)
__device__ float g_esum[K_CODES * D_DIM];
__device__ float g_counts[K_CODES];
__device__ float g_commit;
__device__ float g_ee[K_CODES];
__device__ float g_invcs[K_CODES];

// ---------------------------------------------------------------------------
__global__ void init_zero_kernel() {
    int i = blockIdx.x * blockDim.x + threadIdx.x;
    if (i < K_CODES * D_DIM)                     g_esum[i] = 0.f;
    else if (i < K_CODES * D_DIM + K_CODES)      g_counts[i - K_CODES * D_DIM] = 0.f;
    else if (i == K_CODES * D_DIM + K_CODES)     g_commit = 0.f;
}

// ||e_k||^2 per code, one warp per code
__global__ void __launch_bounds__(1024) embed_norm_kernel(const float* __restrict__ embed) {
    int wid = threadIdx.x >> 5, lane = threadIdx.x & 31;
    int k = blockIdx.x * 32 + wid;
    const float* e = embed + (size_t)k * D_DIM;
    float s = 0.f;
#pragma unroll
    for (int j = 0; j < 8; j++) { float v = e[lane + 32 * j]; s += v * v; }
#pragma unroll
    for (int o = 16; o; o >>= 1) s += __shfl_xor_sync(0xffffffffu, s, o);
    if (lane == 0) g_ee[k] = s;
}

// ---------------------------------------------------------------------------
// Main fused kernel: distances + argmin + softmax + z_q + commitment + segsums
// Block: 256 threads, BM=64 rows, loops over all K in BN=64 tiles.
__global__ void __launch_bounds__(256) dist_kernel(
    const float* __restrict__ z, const float* __restrict__ embed,
    float* __restrict__ out)
{
    extern __shared__ float sm[];
    float* zs  = sm;                    // [256][68] z tile, transposed (d-major)
    float* es  = zs + 256 * 68;         // [256][68] embed tile, transposed
    float* stg = es + 256 * 68;         // [64][68]  dist staging for coalesced STG
    float* zz  = stg + 64 * 68;         // [64] row |z|^2
    float* red = zz + 64;               // [8] commit-loss warp partials
    unsigned long long* rowred = (unsigned long long*)(red + 8);  // [64] packed min

    const int tid  = threadIdx.x;
    const int brow = blockIdx.x * BM;

    if (tid < 64) { zz[tid] = 0.f; rowred[tid] = ~0ull; }
    __syncthreads();

    // Load z tile (transposed) + per-row squared norms
    {
        int row = tid >> 2, q = tid & 3;
        const float4* zg = (const float4*)(z + (size_t)(brow + row) * D_DIM);
        float s = 0.f;
#pragma unroll
        for (int j = 0; j < 16; j++) {
            float4 v = zg[q * 16 + j];
            int d = (q * 16 + j) * 4;
            zs[(d + 0) * 68 + row] = v.x; zs[(d + 1) * 68 + row] = v.y;
            zs[(d + 2) * 68 + row] = v.z; zs[(d + 3) * 68 + row] = v.w;
            s += v.x * v.x + v.y * v.y + v.z * v.z + v.w * v.w;
        }
        atomicAdd(&zz[row], s);
    }
    __syncthreads();

    const int ty = tid >> 4, tx = tid & 15;
    const int r0 = ty * 4, c0 = tx * 4;
    float minv[4] = {3.4e38f, 3.4e38f, 3.4e38f, 3.4e38f};
    int   mini[4] = {0, 0, 0, 0};

    float* sa = out + OFF_SA + (size_t)brow * K_CODES;

    for (int kb = 0; kb < K_CODES; kb += BN) {
        // Load embed tile (transposed)
        {
            int col = tid >> 2, q = tid & 3;
            const float4* eg = (const float4*)(embed + (size_t)(kb + col) * D_DIM);
#pragma unroll
            for (int j = 0; j < 16; j++) {
                float4 v = eg[q * 16 + j];
                int d = (q * 16 + j) * 4;
                es[(d + 0) * 68 + col] = v.x; es[(d + 1) * 68 + col] = v.y;
                es[(d + 2) * 68 + col] = v.z; es[(d + 3) * 68 + col] = v.w;
            }
        }
        __syncthreads();

        float acc[4][4];
#pragma unroll
        for (int i = 0; i < 4; i++)
#pragma unroll
            for (int j = 0; j < 4; j++) acc[i][j] = 0.f;

#pragma unroll 8
        for (int d = 0; d < D_DIM; d++) {
            float4 zf = *(const float4*)(zs + d * 68 + r0);
            float4 ef = *(const float4*)(es + d * 68 + c0);
            float za[4] = {zf.x, zf.y, zf.z, zf.w};
            float eb[4] = {ef.x, ef.y, ef.z, ef.w};
#pragma unroll
            for (int i = 0; i < 4; i++)
#pragma unroll
                for (int j = 0; j < 4; j++) acc[i][j] += za[i] * eb[j];
        }

        // Epilogue: dist = |z|^2 + |e|^2 - 2 z.e ; track min ; stage
        float eev[4];
#pragma unroll
        for (int j = 0; j < 4; j++) eev[j] = g_ee[kb + c0 + j];
#pragma unroll
        for (int i = 0; i < 4; i++) {
            float zzi = zz[r0 + i];
#pragma unroll
            for (int j = 0; j < 4; j++) {
                float dist = zzi + eev[j] - 2.f * acc[i][j];
                stg[(r0 + i) * 68 + c0 + j] = dist;
                if (dist < minv[i]) { minv[i] = dist; mini[i] = kb + c0 + j; }
            }
        }
        __syncthreads();
        // Coalesced copy staging -> gmem (soft_assign slot, raw dist for now)
        for (int idx = tid; idx < BM * BN; idx += 256) {
            int rr = idx >> 6, cc = idx & 63;
            sa[(size_t)rr * K_CODES + kb + cc] = stg[rr * 68 + cc];
        }
        __syncthreads();
    }

    // Row-wise argmin reduce: packed (ordered-float-bits << 32 | k), min => first-min semantics
#pragma unroll
    for (int i = 0; i < 4; i++) {
        unsigned int b = __float_as_uint(minv[i]);
        unsigned int eb = (b & 0x80000000u) ? ~b : (b ^ 0x80000000u);
        unsigned long long p = ((unsigned long long)eb << 32) | (unsigned int)mini[i];
        atomicMin(&rowred[r0 + i], p);
    }
    __syncthreads();

    // Phase B: per-warp softmax + z_q + commit + segment sums. 8 warps x 8 rows.
    const int wid = tid >> 5, lane = tid & 31;
    float commit_acc = 0.f;
    const float C = 14.4269504088896341f;   // 10 / ln(2)

    for (int rr = 0; rr < 8; rr++) {
        int row = wid * 8 + rr;
        unsigned long long p = rowred[row];
        unsigned int eb = (unsigned int)(p >> 32);
        unsigned int b  = (eb & 0x80000000u) ? (eb ^ 0x80000000u) : ~eb;
        float dmin = __uint_as_float(b);
        int code = (int)(p & 0xFFFFFFFFu);

        float* sarow = sa + (size_t)row * K_CODES;
        float s = 0.f;
#pragma unroll 4
        for (int it = 0; it < 32; it++) {
            float dv = sarow[lane + it * 32];
            s += exp2f((dmin - dv) * C);
        }
#pragma unroll
        for (int o = 16; o; o >>= 1) s += __shfl_xor_sync(0xffffffffu, s, o);
        float invs = 1.0f / s;
#pragma unroll 4
        for (int it = 0; it < 32; it++) {
            float dv = sarow[lane + it * 32];
            sarow[lane + it * 32] = exp2f((dmin - dv) * C) * invs;
        }

        int grow = brow + row;
        const float* erow = embed + (size_t)code * D_DIM;
        float* zqrow = out + OFF_ZQ + (size_t)grow * D_DIM;
        float* esrow = g_esum + (size_t)code * D_DIM;
#pragma unroll
        for (int it = 0; it < 8; it++) {
            int d = lane + it * 32;
            float ev = erow[d];
            float zv = zs[d * 68 + row];
            zqrow[d] = ev;
            float df = zv - ev;
            commit_acc += df * df;
            atomicAdd(&esrow[d], zv);
        }
        if (lane == 0) {
            atomicAdd(&g_counts[code], 1.0f);
            out[OFF_CODES + grow] = (float)code;
        }
    }
#pragma unroll
    for (int o = 16; o; o >>= 1) commit_acc += __shfl_xor_sync(0xffffffffu, commit_acc, o);
    if (lane == 0) red[wid] = commit_acc;
    __syncthreads();
    if (tid == 0) {
        float t = 0.f;
        for (int w = 0; w < 8; w++) t += red[w];
        atomicAdd(&g_commit, t);
    }
}

// ---------------------------------------------------------------------------
// EMA scalar/vector updates (one block, 1024 threads = one per code)
__global__ void __launch_bounds__(1024) ema_kernel(const float* __restrict__ cs,
                                                   float* __restrict__ out) {
    __shared__ float sh[33];
    int t = threadIdx.x, lane = t & 31, wid = t >> 5;

    float cnt = g_counts[t];
    float ncs = 0.99f * cs[t] + 0.01f * cnt;
    out[OFF_CS + t] = ncs;

    // reduce n = sum(new_cluster_size)
    float v = ncs;
#pragma unroll
    for (int o = 16; o; o >>= 1) v += __shfl_xor_sync(0xffffffffu, v, o);
    if (lane == 0) sh[wid] = v;
    __syncthreads();
    if (t < 32) {
        float r = sh[t];
#pragma unroll
        for (int o = 16; o; o >>= 1) r += __shfl_xor_sync(0xffffffffu, r, o);
        if (t == 0) sh[32] = r;
    }
    __syncthreads();
    float n = sh[32];
    __syncthreads();

    // entropy / perplexity from counts
    float avg = cnt * (1.0f / (float)N_TOK);
    float term = -avg * logf(avg + 1e-10f);
    v = term;
#pragma unroll
    for (int o = 16; o; o >>= 1) v += __shfl_xor_sync(0xffffffffu, v, o);
    if (lane == 0) sh[wid] = v;
    __syncthreads();
    if (t < 32) {
        float r = sh[t];
#pragma unroll
        for (int o = 16; o; o >>= 1) r += __shfl_xor_sync(0xffffffffu, r, o);
        if (t == 0) {
            out[OFF_ENT]  = r;
            out[OFF_PERP] = expf(r);
            out[OFF_LOSS] = g_commit * (1.0f / 8388608.0f);  // mean over N*D
        }
    }

    float csn = (ncs + 1e-5f) / (n + 1024.0f * 1e-5f) * n;
    g_invcs[t] = 1.0f / csn;
}

__global__ void __launch_bounds__(1024) embed_update_kernel(const float* __restrict__ ea,
                                                            float* __restrict__ out) {
    int i = blockIdx.x * 1024 + threadIdx.x;   // 262144 total
    float v = 0.99f * ea[i] + 0.01f * g_esum[i];
    out[OFF_EA + i] = v;
    out[OFF_EMBED + i] = v * g_invcs[i >> 8];
}

// ---------------------------------------------------------------------------
extern "C" void kernel_launch(void* const* d_in, const int* in_sizes, int n_in,
                              void* d_out, int out_size) {
    const float* z     = (const float*)d_in[0];
    const float* embed = (const float*)d_in[1];
    const float* cs    = (const float*)d_in[2];
    const float* ea    = (const float*)d_in[3];
    float* out = (float*)d_out;

    const int SMEM = (256 * 68 + 256 * 68 + 64 * 68 + 64 + 8) * 4 + 64 * 8;  // 157472 B
    cudaFuncSetAttribute(dist_kernel, cudaFuncAttributeMaxDynamicSharedMemorySize, SMEM);

    init_zero_kernel<<<258, 1024>>>();
    embed_norm_kernel<<<32, 1024>>>(embed);
    dist_kernel<<<N_TOK / BM, 256, SMEM>>>(z, embed, out);
    ema_kernel<<<1, 1024>>>(cs, out);
    embed_update_kernel<<<256, 1024>>>(ea, out);
    (void)in_sizes; (void)n_in; (void)out_size;
}

// round 8
// speedup vs baseline: 2.6881x; 2.6881x over previous
#include <cuda_runtime.h>
#include <cuda_bf16.h>
#include <cstdint>

#define N_TOK   32768
#define K_CODES 1024
#define D_DIM   256

// Output layout: reference tuple concatenated as float32 in return order.
#define OFF_ZQ    0ull
#define OFF_CODES 8388608ull
#define OFF_LOSS  8421376ull
#define OFF_PERP  8421377ull
#define OFF_ENT   8421378ull
#define OFF_SA    8421379ull
#define OFF_EMBED 41975811ull
#define OFF_CS    42237955ull
#define OFF_EA    42238979ull

// ---------------------------------------------------------------------------
// Scratch (__device__ globals; no runtime allocation allowed)
__device__ float g_esum[K_CODES * D_DIM];
__device__ float g_counts[K_CODES];
__device__ float g_commit;
__device__ float g_ee[K_CODES];
__device__ float g_invcs[K_CODES];
__device__ __align__(16) unsigned short g_eh[K_CODES * D_DIM];  // embed bf16 hi
__device__ __align__(16) unsigned short g_el[K_CODES * D_DIM];  // embed bf16 lo

// ---------------------------------------------------------------------------
__device__ __forceinline__ uint32_t smem_u32(const void* p) {
    uint32_t a;
    asm("{ .reg .u64 t; cvta.to.shared.u64 t, %1; cvt.u32.u64 %0, t; }" : "=r"(a) : "l"(p));
    return a;
}
__device__ __forceinline__ float ex2(float x) {
    float r; asm("ex2.approx.ftz.f32 %0, %1;" : "=f"(r) : "f"(x)); return r;
}
#define SWZ(o) ((o) ^ (((o) >> 3) & 0x70u))

#define LDSM4(r, a) \
    asm volatile("ldmatrix.sync.aligned.m8n8.x4.shared.b16 {%0,%1,%2,%3}, [%4];" \
        : "=r"((r)[0]), "=r"((r)[1]), "=r"((r)[2]), "=r"((r)[3]) : "r"(a))
#define LDSM2(r, a) \
    asm volatile("ldmatrix.sync.aligned.m8n8.x2.shared.b16 {%0,%1}, [%2];" \
        : "=r"((r)[0]), "=r"((r)[1]) : "r"(a))
#define MMA16816(d, a, b) \
    asm volatile("mma.sync.aligned.m16n8k16.row.col.f32.bf16.bf16.f32 " \
        "{%0,%1,%2,%3},{%4,%5,%6,%7},{%8,%9},{%0,%1,%2,%3};" \
        : "+f"((d)[0]), "+f"((d)[1]), "+f"((d)[2]), "+f"((d)[3]) \
        : "r"((a)[0]), "r"((a)[1]), "r"((a)[2]), "r"((a)[3]), "r"((b)[0]), "r"((b)[1]))

__device__ __forceinline__ unsigned short f2bf(float v) {
    __nv_bfloat16 b = __float2bfloat16(v);
    return *reinterpret_cast<unsigned short*>(&b);
}
__device__ __forceinline__ float bf2f(unsigned short u) {
    __nv_bfloat16 b = *reinterpret_cast<__nv_bfloat16*>(&u);
    return __bfloat162float(b);
}

// ---------------------------------------------------------------------------
__global__ void init_zero_kernel() {
    int i = blockIdx.x * blockDim.x + threadIdx.x;
    if (i < K_CODES * D_DIM)                 g_esum[i] = 0.f;
    else if (i < K_CODES * D_DIM + K_CODES)  g_counts[i - K_CODES * D_DIM] = 0.f;
    else if (i == K_CODES * D_DIM + K_CODES) g_commit = 0.f;
}

// embed -> bf16 hi/lo split + squared norms. One warp per code.
__global__ void __launch_bounds__(256) embed_prep_kernel(const float* __restrict__ embed) {
    int w = threadIdx.x >> 5, lane = threadIdx.x & 31;
    int k = blockIdx.x * 8 + w;
    const float* e = embed + (size_t)k * D_DIM;
    float s = 0.f;
#pragma unroll
    for (int j = 0; j < 8; j++) {
        int d = lane + 32 * j;
        float v = e[d];
        unsigned short h = f2bf(v);
        unsigned short l = f2bf(v - bf2f(h));
        g_eh[k * D_DIM + d] = h;
        g_el[k * D_DIM + d] = l;
        s += v * v;
    }
#pragma unroll
    for (int o = 16; o; o >>= 1) s += __shfl_xor_sync(0xffffffffu, s, o);
    if (lane == 0) g_ee[k] = s;
}

// ---------------------------------------------------------------------------
// SMEM layout (bytes)
#define SM_RED  0u       // 8 floats
#define SM_ZZ   64u      // 128 floats
#define SM_EE   576u     // 128 floats
#define SM_PM   1088u    // 256 floats (per-row, per-warp-half min)
#define SM_PS   2112u    // 256 floats (sums)
#define SM_PI   3136u    // 256 ints   (argmin)
#define SM_FM   4160u    // 128 floats final min
#define SM_FS   4672u    // 128 floats final sum
#define SM_FI   5184u    // 128 ints   final idx
#define SM_Z    8192u    // 8 tiles (hi c0..c3, lo c0..c3) x 16384 = 131072
#define SM_E    139264u  // 2 tiles (hi, lo) x 16384 = 32768
#define SMEM_BYTES 172032u

// merge two online-softmax states
__device__ __forceinline__ void osm_merge(float& m, float& s, int& i,
                                          float om, float os, int oi, float C) {
    if (om < m || (om == m && oi < i)) {
        s = os + s * ex2((om - m) * C);
        m = om; i = oi;
    } else {
        s = s + os * ex2((m - om) * C);
    }
}

__global__ void __launch_bounds__(256) dist_kernel(
    const float* __restrict__ z, const float* __restrict__ embed,
    float* __restrict__ out)
{
    extern __shared__ char smem[];
    const uint32_t sb = smem_u32(smem);
    const int tid = threadIdx.x;
    const int w = tid >> 5, lane = tid & 31;
    const int wm = w & 3, wn = w >> 2;        // warp grid 4 (M) x 2 (N)
    const int brow = blockIdx.x * 128;
    const float C = 14.4269504088896341f;      // 10 / ln(2)

    float* red  = (float*)(smem + SM_RED);
    float* zz   = (float*)(smem + SM_ZZ);
    float* ee_s = (float*)(smem + SM_EE);
    float* pm   = (float*)(smem + SM_PM);
    float* ps   = (float*)(smem + SM_PS);
    int*   pi   = (int*)  (smem + SM_PI);
    float* fm   = (float*)(smem + SM_FM);
    float* fs   = (float*)(smem + SM_FS);
    int*   fi   = (int*)  (smem + SM_FI);

    if (tid < 128) zz[tid] = 0.f;
    __syncthreads();

    // ---- load z tile [128 x 256] -> bf16 hi/lo split, swizzled smem, row norms
    {
        int r = tid >> 1, hf = tid & 1;
        float s = 0.f;
#pragma unroll
        for (int j = 0; j < 16; j++) {
            int d = hf * 128 + j * 8;
            const float4* zp = (const float4*)(z + (size_t)(brow + r) * D_DIM + d);
            float4 a = zp[0], b = zp[1];
            float f[8] = {a.x, a.y, a.z, a.w, b.x, b.y, b.z, b.w};
            uint32_t hv[4], lv[4];
#pragma unroll
            for (int q = 0; q < 4; q++) {
                unsigned short h0 = f2bf(f[2*q]),   h1 = f2bf(f[2*q+1]);
                unsigned short l0 = f2bf(f[2*q]   - bf2f(h0));
                unsigned short l1 = f2bf(f[2*q+1] - bf2f(h1));
                hv[q] = (uint32_t)h0 | ((uint32_t)h1 << 16);
                lv[q] = (uint32_t)l0 | ((uint32_t)l1 << 16);
                s += f[2*q]*f[2*q] + f[2*q+1]*f[2*q+1];
            }
            int chunk = d >> 6, col = d & 63;
            uint32_t off = SWZ((uint32_t)(r * 128 + col * 2));
            *(uint4*)(smem + SM_Z + chunk       * 16384 + off) = make_uint4(hv[0],hv[1],hv[2],hv[3]);
            *(uint4*)(smem + SM_Z + (4 + chunk) * 16384 + off) = make_uint4(lv[0],lv[1],lv[2],lv[3]);
        }
        atomicAdd(&zz[r], s);
    }
    __syncthreads();

    const int g  = lane >> 2;           // fragment row-in-8
    const int t2 = (lane & 3) * 2;      // fragment col pair
    // zz for the 4 rows this thread owns: (tm, half)
    float zzr[4];
#pragma unroll
    for (int tm = 0; tm < 2; tm++) {
        zzr[tm*2 + 0] = zz[wm*32 + tm*16 + g];
        zzr[tm*2 + 1] = zz[wm*32 + tm*16 + g + 8];
    }

    // online softmax state per owned row-slot
    float osm_m[4] = {3.4e38f, 3.4e38f, 3.4e38f, 3.4e38f};
    float osm_s[4] = {0.f, 0.f, 0.f, 0.f};
    int   osm_i[4] = {0, 0, 0, 0};

    for (int nt = 0; nt < 8; nt++) {
        float acc[2][8][4];
#pragma unroll
        for (int tm = 0; tm < 2; tm++)
#pragma unroll
            for (int tn = 0; tn < 8; tn++)
#pragma unroll
                for (int q = 0; q < 4; q++) acc[tm][tn][q] = 0.f;

        for (int c = 0; c < 4; c++) {
            __syncthreads();   // protect e buffer + ee_s from previous readers
            // load embed chunk (hi+lo), 32 KB
#pragma unroll
            for (int m = 0; m < 8; m++) {
                int linear = m * 256 + tid;
                int s = linear >> 10, rem = linear & 1023;
                int i = rem >> 3, grp = rem & 7;
                const unsigned short* src = s ? g_el : g_eh;
                uint4 v = *(const uint4*)(src + ((size_t)(nt * 128 + i) * D_DIM + c * 64 + grp * 8));
                uint32_t off = SWZ((uint32_t)(i * 128 + grp * 16));
                *(uint4*)(smem + SM_E + s * 16384 + off) = v;
            }
            if (c == 0 && tid < 128) ee_s[tid] = g_ee[nt * 128 + tid];
            __syncthreads();

#pragma unroll
            for (int ks = 0; ks < 4; ks++) {
                // A fragments (hi + lo) for both 16-row tiles
                uint32_t ah[2][4], al[2][4];
#pragma unroll
                for (int tm = 0; tm < 2; tm++) {
                    int row = wm * 32 + tm * 16 + (lane & 15);
                    uint32_t kg = (uint32_t)(ks * 2 + (lane >> 4));
                    uint32_t boff = (uint32_t)(row * 128) + ((kg ^ (row & 7)) << 4);
                    LDSM4(ah[tm], sb + SM_Z + (0 + c) * 16384 + boff);
                    LDSM4(al[tm], sb + SM_Z + (4 + c) * 16384 + boff);
                }
#pragma unroll
                for (int tnh = 0; tnh < 2; tnh++) {
                    uint32_t bh[4][2], bl[4][2];
#pragma unroll
                    for (int j = 0; j < 4; j++) {
                        int n0 = wn * 64 + (tnh * 4 + j) * 8;
                        int row = n0 + (lane & 7);
                        uint32_t kg = (uint32_t)(ks * 2 + ((lane >> 3) & 1));
                        uint32_t boff = (uint32_t)(row * 128) + ((kg ^ (row & 7)) << 4);
                        LDSM2(bh[j], sb + SM_E + 0 * 16384 + boff);
                        LDSM2(bl[j], sb + SM_E + 1 * 16384 + boff);
                    }
                    // hh, then hl, then lh — same-acc reuse distance 8
#pragma unroll
                    for (int j = 0; j < 4; j++)
#pragma unroll
                        for (int tm = 0; tm < 2; tm++) MMA16816(acc[tm][tnh*4+j], ah[tm], bh[j]);
#pragma unroll
                    for (int j = 0; j < 4; j++)
#pragma unroll
                        for (int tm = 0; tm < 2; tm++) MMA16816(acc[tm][tnh*4+j], ah[tm], bl[j]);
#pragma unroll
                    for (int j = 0; j < 4; j++)
#pragma unroll
                        for (int tm = 0; tm < 2; tm++) MMA16816(acc[tm][tnh*4+j], al[tm], bh[j]);
                }
            }
        }

        // ---- epilogue: dist, online softmax, direct STG to soft_assign slot
        // NOTE: OFF_SA is an ODD float offset -> sa rows are only 4B-aligned.
        // All stores here must be scalar 32-bit.
#pragma unroll
        for (int tm = 0; tm < 2; tm++) {
            int r_lo = wm * 32 + tm * 16 + g;
#pragma unroll
            for (int tn = 0; tn < 8; tn++) {
                int col = wn * 64 + tn * 8 + t2;
                int gc  = nt * 128 + col;
                float ee0 = ee_s[col], ee1 = ee_s[col + 1];
                float d00 = zzr[tm*2+0] + ee0 - 2.f * acc[tm][tn][0];
                float d01 = zzr[tm*2+0] + ee1 - 2.f * acc[tm][tn][1];
                float d10 = zzr[tm*2+1] + ee0 - 2.f * acc[tm][tn][2];
                float d11 = zzr[tm*2+1] + ee1 - 2.f * acc[tm][tn][3];

                int s0 = tm * 2, s1 = tm * 2 + 1;
                if (d00 < osm_m[s0]) { osm_s[s0] = osm_s[s0] * ex2((d00 - osm_m[s0]) * C) + 1.f; osm_m[s0] = d00; osm_i[s0] = gc; }
                else osm_s[s0] += ex2((osm_m[s0] - d00) * C);
                if (d01 < osm_m[s0]) { osm_s[s0] = osm_s[s0] * ex2((d01 - osm_m[s0]) * C) + 1.f; osm_m[s0] = d01; osm_i[s0] = gc + 1; }
                else osm_s[s0] += ex2((osm_m[s0] - d01) * C);
                if (d10 < osm_m[s1]) { osm_s[s1] = osm_s[s1] * ex2((d10 - osm_m[s1]) * C) + 1.f; osm_m[s1] = d10; osm_i[s1] = gc; }
                else osm_s[s1] += ex2((osm_m[s1] - d10) * C);
                if (d11 < osm_m[s1]) { osm_s[s1] = osm_s[s1] * ex2((d11 - osm_m[s1]) * C) + 1.f; osm_m[s1] = d11; osm_i[s1] = gc + 1; }
                else osm_s[s1] += ex2((osm_m[s1] - d11) * C);

                float* p0 = out + OFF_SA + (size_t)(brow + r_lo) * K_CODES + gc;
                float* p1 = out + OFF_SA + (size_t)(brow + r_lo + 8) * K_CODES + gc;
                p0[0] = d00; p0[1] = d01;
                p1[0] = d10; p1[1] = d11;
            }
        }
    }

    // ---- merge online states: lanes (xor 1,2) then across the two warp-halves
#pragma unroll
    for (int sl = 0; sl < 4; sl++) {
        float m = osm_m[sl], s = osm_s[sl]; int i = osm_i[sl];
#pragma unroll
        for (int off = 1; off <= 2; off <<= 1) {
            float om = __shfl_xor_sync(0xffffffffu, m, off);
            float os = __shfl_xor_sync(0xffffffffu, s, off);
            int   oi = __shfl_xor_sync(0xffffffffu, i, off);
            osm_merge(m, s, i, om, os, oi, C);
        }
        if ((lane & 3) == 0) {
            int row = wm * 32 + (sl >> 1) * 16 + g + (sl & 1) * 8;
            pm[row * 2 + wn] = m; ps[row * 2 + wn] = s; pi[row * 2 + wn] = i;
        }
    }
    __syncthreads();
    if (tid < 128) {
        float m = pm[tid * 2], s = ps[tid * 2]; int i = pi[tid * 2];
        osm_merge(m, s, i, pm[tid * 2 + 1], ps[tid * 2 + 1], pi[tid * 2 + 1], C);
        fm[tid] = m; fs[tid] = s; fi[tid] = i;
    }
    __syncthreads();

    // ---- Phase B: single-pass softmax normalize + z_q + commitment + segsums
    float commit_acc = 0.f;
    for (int rr = 0; rr < 16; rr++) {
        int row = w * 16 + rr;
        float dmin = fm[row];
        float invs = 1.0f / fs[row];
        int   code = fi[row];
        int grow = brow + row;

        float* sarow = out + OFF_SA + (size_t)grow * K_CODES;
#pragma unroll 4
        for (int it = 0; it < 32; it++) {
            int i = lane + it * 32;
            float d = sarow[i];
            sarow[i] = ex2((dmin - d) * C) * invs;
        }

        const float* erow = embed + (size_t)code * D_DIM;
        const float* zrow = z + (size_t)grow * D_DIM;
        float* zqrow = out + OFF_ZQ + (size_t)grow * D_DIM;
        float* esrow = g_esum + (size_t)code * D_DIM;
#pragma unroll
        for (int it = 0; it < 8; it++) {
            int d = lane + it * 32;
            float ev = erow[d];
            float zv = zrow[d];
            zqrow[d] = ev;
            float df = zv - ev;
            commit_acc += df * df;
            atomicAdd(&esrow[d], zv);
        }
        if (lane == 0) {
            atomicAdd(&g_counts[code], 1.0f);
            out[OFF_CODES + grow] = (float)code;
        }
    }
#pragma unroll
    for (int o = 16; o; o >>= 1) commit_acc += __shfl_xor_sync(0xffffffffu, commit_acc, o);
    if (lane == 0) red[w] = commit_acc;
    __syncthreads();
    if (tid == 0) {
        float t = 0.f;
        for (int i = 0; i < 8; i++) t += red[i];
        atomicAdd(&g_commit, t);
    }
}

// ---------------------------------------------------------------------------
__global__ void __launch_bounds__(1024) ema_kernel(const float* __restrict__ cs,
                                                   float* __restrict__ out) {
    __shared__ float sh[33];
    int t = threadIdx.x, lane = t & 31, wid = t >> 5;

    float cnt = g_counts[t];
    float ncs = 0.99f * cs[t] + 0.01f * cnt;
    out[OFF_CS + t] = ncs;

    float v = ncs;
#pragma unroll
    for (int o = 16; o; o >>= 1) v += __shfl_xor_sync(0xffffffffu, v, o);
    if (lane == 0) sh[wid] = v;
    __syncthreads();
    if (t < 32) {
        float r = sh[t];
#pragma unroll
        for (int o = 16; o; o >>= 1) r += __shfl_xor_sync(0xffffffffu, r, o);
        if (t == 0) sh[32] = r;
    }
    __syncthreads();
    float n = sh[32];
    __syncthreads();

    float avg = cnt * (1.0f / (float)N_TOK);
    float term = -avg * logf(avg + 1e-10f);
    v = term;
#pragma unroll
    for (int o = 16; o; o >>= 1) v += __shfl_xor_sync(0xffffffffu, v, o);
    if (lane == 0) sh[wid] = v;
    __syncthreads();
    if (t < 32) {
        float r = sh[t];
#pragma unroll
        for (int o = 16; o; o >>= 1) r += __shfl_xor_sync(0xffffffffu, r, o);
        if (t == 0) {
            out[OFF_ENT]  = r;
            out[OFF_PERP] = expf(r);
            out[OFF_LOSS] = g_commit * (1.0f / 8388608.0f);
        }
    }
    float csn = (ncs + 1e-5f) / (n + 1024.0f * 1e-5f) * n;
    g_invcs[t] = 1.0f / csn;
}

__global__ void __launch_bounds__(1024) embed_update_kernel(const float* __restrict__ ea,
                                                            float* __restrict__ out) {
    int i = blockIdx.x * 1024 + threadIdx.x;
    float v = 0.99f * ea[i] + 0.01f * g_esum[i];
    out[OFF_EA + i] = v;
    out[OFF_EMBED + i] = v * g_invcs[i >> 8];
}

// ---------------------------------------------------------------------------
extern "C" void kernel_launch(void* const* d_in, const int* in_sizes, int n_in,
                              void* d_out, int out_size) {
    const float* z     = (const float*)d_in[0];
    const float* embed = (const float*)d_in[1];
    const float* cs    = (const float*)d_in[2];
    const float* ea    = (const float*)d_in[3];
    float* out = (float*)d_out;

    cudaFuncSetAttribute(dist_kernel, cudaFuncAttributeMaxDynamicSharedMemorySize, SMEM_BYTES);

    init_zero_kernel<<<258, 1024>>>();
    embed_prep_kernel<<<128, 256>>>(embed);
    dist_kernel<<<N_TOK / 128, 256, SMEM_BYTES>>>(z, embed, out);
    ema_kernel<<<1, 1024>>>(cs, out);
    embed_update_kernel<<<256, 1024>>>(ea, out);
    (void)in_sizes; (void)n_in; (void)out_size;
}

// round 11
// speedup vs baseline: 2.9481x; 1.0967x over previous
#include <cuda_runtime.h>
#include <cuda_bf16.h>
#include <cstdint>

#define N_TOK   32768
#define K_CODES 1024
#define D_DIM   256

// Output layout: reference tuple concatenated as float32 in return order.
#define OFF_ZQ    0ull
#define OFF_CODES 8388608ull
#define OFF_LOSS  8421376ull
#define OFF_PERP  8421377ull
#define OFF_ENT   8421378ull
#define OFF_SA    8421379ull
#define OFF_EMBED 41975811ull
#define OFF_CS    42237955ull
#define OFF_EA    42238979ull

// ---------------------------------------------------------------------------
// Scratch (__device__ globals; no runtime allocation allowed)
__device__ float g_esum[K_CODES * D_DIM];
__device__ float g_counts[K_CODES];
__device__ float g_commit;
__device__ float g_ee[K_CODES];
__device__ float g_invcs[K_CODES];
__device__ __align__(16) unsigned short g_eh[K_CODES * D_DIM];  // embed bf16 hi
__device__ __align__(16) unsigned short g_el[K_CODES * D_DIM];  // embed bf16 lo

// ---------------------------------------------------------------------------
__device__ __forceinline__ uint32_t smem_u32(const void* p) {
    uint32_t a;
    asm("{ .reg .u64 t; cvta.to.shared.u64 t, %1; cvt.u32.u64 %0, t; }" : "=r"(a) : "l"(p));
    return a;
}
__device__ __forceinline__ float ex2(float x) {
    float r; asm("ex2.approx.ftz.f32 %0, %1;" : "=f"(r) : "f"(x)); return r;
}
#define SWZ(o) ((o) ^ (((o) >> 3) & 0x70u))

#define LDSM4(r, a) \
    asm volatile("ldmatrix.sync.aligned.m8n8.x4.shared.b16 {%0,%1,%2,%3}, [%4];" \
        : "=r"((r)[0]), "=r"((r)[1]), "=r"((r)[2]), "=r"((r)[3]) : "r"(a))
#define MMA16816(d, a, b) \
    asm volatile("mma.sync.aligned.m16n8k16.row.col.f32.bf16.bf16.f32 " \
        "{%0,%1,%2,%3},{%4,%5,%6,%7},{%8,%9},{%0,%1,%2,%3};" \
        : "+f"((d)[0]), "+f"((d)[1]), "+f"((d)[2]), "+f"((d)[3]) \
        : "r"((a)[0]), "r"((a)[1]), "r"((a)[2]), "r"((a)[3]), "r"((b)[0]), "r"((b)[1]))

#define CP_ASYNC16(saddr, gptr) \
    asm volatile("cp.async.cg.shared.global [%0], [%1], 16;" :: "r"(saddr), "l"(gptr))
#define CP_COMMIT() asm volatile("cp.async.commit_group;" ::: "memory")
#define CP_WAIT(n)  asm volatile("cp.async.wait_group %0;" :: "n"(n) : "memory")

__device__ __forceinline__ unsigned short f2bf(float v) {
    __nv_bfloat16 b = __float2bfloat16(v);
    return *reinterpret_cast<unsigned short*>(&b);
}
__device__ __forceinline__ float bf2f(unsigned short u) {
    __nv_bfloat16 b = *reinterpret_cast<__nv_bfloat16*>(&u);
    return __bfloat162float(b);
}

// ---------------------------------------------------------------------------
__global__ void init_zero_kernel() {
    int i = blockIdx.x * blockDim.x + threadIdx.x;
    if (i < K_CODES * D_DIM)                 g_esum[i] = 0.f;
    else if (i < K_CODES * D_DIM + K_CODES)  g_counts[i - K_CODES * D_DIM] = 0.f;
    else if (i == K_CODES * D_DIM + K_CODES) g_commit = 0.f;
}

// embed -> bf16 hi/lo split + squared norms. One warp per code.
__global__ void __launch_bounds__(256) embed_prep_kernel(const float* __restrict__ embed) {
    int w = threadIdx.x >> 5, lane = threadIdx.x & 31;
    int k = blockIdx.x * 8 + w;
    const float* e = embed + (size_t)k * D_DIM;
    float s = 0.f;
#pragma unroll
    for (int j = 0; j < 8; j++) {
        int d = lane + 32 * j;
        float v = e[d];
        unsigned short h = f2bf(v);
        unsigned short l = f2bf(v - bf2f(h));
        g_eh[k * D_DIM + d] = h;
        g_el[k * D_DIM + d] = l;
        s += v * v;
    }
#pragma unroll
    for (int o = 16; o; o >>= 1) s += __shfl_xor_sync(0xffffffffu, s, o);
    if (lane == 0) g_ee[k] = s;
}

// ---------------------------------------------------------------------------
// SMEM layout (bytes)
#define SM_RED  0u       // 8 floats
#define SM_ZZ   64u      // 128 floats = 512B
#define SM_PM   576u     // 256 floats
#define SM_PS   1600u    // 256 floats
#define SM_PI   2624u    // 256 ints
#define SM_FM   3648u    // 128 floats
#define SM_FS   4160u    // 128 floats
#define SM_FI   4672u    // 128 ints
#define SM_EE   5184u    // 1024 floats (all code norms) = 4096B, ends 9280
#define SM_Z    10240u   // 8 tiles (hi c0..c3, lo c0..c3) x 16384 = 131072, ends 141312
#define SM_E    141312u  // 2 chunk buffers x (hi 16384 + lo 16384) = 65536
#define SMEM_BYTES 206848u

// merge two online-softmax states
__device__ __forceinline__ void osm_merge(float& m, float& s, int& i,
                                          float om, float os, int oi, float C) {
    if (om < m || (om == m && oi < i)) {
        s = os + s * ex2((om - m) * C);
        m = om; i = oi;
    } else {
        s = s + os * ex2((m - om) * C);
    }
}

// issue async copy of E chunk L (nt = L>>2, c = L&3) into buffer L&1
__device__ __forceinline__ void copy_chunk(uint32_t sb, int L, int tid) {
    int nt = L >> 2, c = L & 3;
    uint32_t dstb = SM_E + (uint32_t)(L & 1) * 32768u;
#pragma unroll
    for (int m = 0; m < 8; m++) {
        int linear = m * 256 + tid;
        int s = linear >> 10, rem = linear & 1023;
        int i = rem >> 3, grp = rem & 7;
        const unsigned short* src = s ? g_el : g_eh;
        const void* gp = (const void*)(src + ((size_t)(nt * 128 + i) * D_DIM + c * 64 + grp * 8));
        uint32_t off = SWZ((uint32_t)(i * 128 + grp * 16));
        CP_ASYNC16(sb + dstb + s * 16384u + off, gp);
    }
}

__global__ void __launch_bounds__(256) dist_kernel(
    const float* __restrict__ z, const float* __restrict__ embed,
    float* __restrict__ out)
{
    extern __shared__ char smem[];
    const uint32_t sb = smem_u32(smem);
    const int tid = threadIdx.x;
    const int w = tid >> 5, lane = tid & 31;
    const int wm = w & 3, wn = w >> 2;        // warp grid 4 (M) x 2 (N)
    const int brow = blockIdx.x * 128;
    const float C = 14.4269504088896341f;      // 10 / ln(2)

    float* red  = (float*)(smem + SM_RED);
    float* zz   = (float*)(smem + SM_ZZ);
    float* ee_s = (float*)(smem + SM_EE);
    float* pm   = (float*)(smem + SM_PM);
    float* ps   = (float*)(smem + SM_PS);
    int*   pi   = (int*)  (smem + SM_PI);
    float* fm   = (float*)(smem + SM_FM);
    float* fs   = (float*)(smem + SM_FS);
    int*   fi   = (int*)  (smem + SM_FI);

    if (tid < 128) zz[tid] = 0.f;
    __syncthreads();

    // kick off E chunk 0 fetch; it overlaps the z-tile load/split below
    copy_chunk(sb, 0, tid);
    CP_COMMIT();

    // ---- load z tile [128 x 256] -> bf16 hi/lo split, swizzled smem, row norms
    {
        int r = tid >> 1, hf = tid & 1;
        float s = 0.f;
#pragma unroll
        for (int j = 0; j < 16; j++) {
            int d = hf * 128 + j * 8;
            const float4* zp = (const float4*)(z + (size_t)(brow + r) * D_DIM + d);
            float4 a = zp[0], b = zp[1];
            float f[8] = {a.x, a.y, a.z, a.w, b.x, b.y, b.z, b.w};
            uint32_t hv[4], lv[4];
#pragma unroll
            for (int q = 0; q < 4; q++) {
                unsigned short h0 = f2bf(f[2*q]),   h1 = f2bf(f[2*q+1]);
                unsigned short l0 = f2bf(f[2*q]   - bf2f(h0));
                unsigned short l1 = f2bf(f[2*q+1] - bf2f(h1));
                hv[q] = (uint32_t)h0 | ((uint32_t)h1 << 16);
                lv[q] = (uint32_t)l0 | ((uint32_t)l1 << 16);
                s += f[2*q]*f[2*q] + f[2*q+1]*f[2*q+1];
            }
            int chunk = d >> 6, col = d & 63;
            uint32_t off = SWZ((uint32_t)(r * 128 + col * 2));
            *(uint4*)(smem + SM_Z + chunk       * 16384 + off) = make_uint4(hv[0],hv[1],hv[2],hv[3]);
            *(uint4*)(smem + SM_Z + (4 + chunk) * 16384 + off) = make_uint4(lv[0],lv[1],lv[2],lv[3]);
        }
        atomicAdd(&zz[r], s);
    }
    // preload ALL code norms once (1024 floats)
#pragma unroll
    for (int k = 0; k < 4; k++) ee_s[tid + k * 256] = g_ee[tid + k * 256];
    __syncthreads();

    const int g  = lane >> 2;           // fragment row-in-8
    const int t2 = (lane & 3) * 2;      // fragment col pair
    float zzr[4];
#pragma unroll
    for (int tm = 0; tm < 2; tm++) {
        zzr[tm*2 + 0] = zz[wm*32 + tm*16 + g];
        zzr[tm*2 + 1] = zz[wm*32 + tm*16 + g + 8];
    }

    // online softmax state per owned row-slot
    float osm_m[4] = {3.4e38f, 3.4e38f, 3.4e38f, 3.4e38f};
    float osm_s[4] = {0.f, 0.f, 0.f, 0.f};
    int   osm_i[4] = {0, 0, 0, 0};

    for (int nt = 0; nt < 8; nt++) {
        float acc[2][8][4];
#pragma unroll
        for (int tm = 0; tm < 2; tm++)
#pragma unroll
            for (int tn = 0; tn < 8; tn++)
#pragma unroll
                for (int q = 0; q < 4; q++) acc[tm][tn][q] = 0.f;

        for (int c = 0; c < 4; c++) {
            const int L = nt * 4 + c;
            // prefetch next chunk into the other buffer (overlaps this chunk's MMA)
            if (L + 1 < 32) {
                copy_chunk(sb, L + 1, tid);
                CP_COMMIT();
                CP_WAIT(1);          // chunk L complete, L+1 in flight
            } else {
                CP_WAIT(0);
            }
            __syncthreads();

            const uint32_t eb = SM_E + (uint32_t)(L & 1) * 32768u;
#pragma unroll
            for (int ks = 0; ks < 4; ks++) {
                // A fragments (hi + lo) for both 16-row tiles
                uint32_t ah[2][4], al[2][4];
#pragma unroll
                for (int tm = 0; tm < 2; tm++) {
                    int row = wm * 32 + tm * 16 + (lane & 15);
                    uint32_t kg = (uint32_t)(ks * 2 + (lane >> 4));
                    uint32_t boff = (uint32_t)(row * 128) + ((kg ^ (row & 7)) << 4);
                    LDSM4(ah[tm], sb + SM_Z + (0 + c) * 16384 + boff);
                    LDSM4(al[tm], sb + SM_Z + (4 + c) * 16384 + boff);
                }
#pragma unroll
                for (int tnh = 0; tnh < 2; tnh++) {
                    // B fragments via x4: 4 matrices = (j-pair) x (k-group)
                    uint32_t bh[4][2], bl[4][2];
#pragma unroll
                    for (int jp = 0; jp < 2; jp++) {
                        int jbase = tnh * 4 + jp * 2;
                        int mi = lane >> 3;                   // matrix index 0..3
                        int row = wn * 64 + (jbase + (mi >> 1)) * 8 + (lane & 7);
                        uint32_t kg = (uint32_t)(ks * 2 + (mi & 1));
                        uint32_t boff = (uint32_t)(row * 128) + ((kg ^ (row & 7)) << 4);
                        uint32_t q[4];
                        LDSM4(q, sb + eb + 0 * 16384 + boff);
                        bh[jp*2+0][0] = q[0]; bh[jp*2+0][1] = q[1];
                        bh[jp*2+1][0] = q[2]; bh[jp*2+1][1] = q[3];
                        LDSM4(q, sb + eb + 1 * 16384 + boff);
                        bl[jp*2+0][0] = q[0]; bl[jp*2+0][1] = q[1];
                        bl[jp*2+1][0] = q[2]; bl[jp*2+1][1] = q[3];
                    }
                    // hh, then hl, then lh — same-acc reuse distance 8
#pragma unroll
                    for (int j = 0; j < 4; j++)
#pragma unroll
                        for (int tm = 0; tm < 2; tm++) MMA16816(acc[tm][tnh*4+j], ah[tm], bh[j]);
#pragma unroll
                    for (int j = 0; j < 4; j++)
#pragma unroll
                        for (int tm = 0; tm < 2; tm++) MMA16816(acc[tm][tnh*4+j], ah[tm], bl[j]);
#pragma unroll
                    for (int j = 0; j < 4; j++)
#pragma unroll
                        for (int tm = 0; tm < 2; tm++) MMA16816(acc[tm][tnh*4+j], al[tm], bh[j]);
                }
            }
            __syncthreads();   // all warps done with buffer (L&1) before it is refilled
        }

        // ---- epilogue: dist, online softmax, direct STG to soft_assign slot
        // NOTE: OFF_SA is an ODD float offset -> sa rows are only 4B-aligned.
        // All stores here must be scalar 32-bit.
#pragma unroll
        for (int tm = 0; tm < 2; tm++) {
            int r_lo = wm * 32 + tm * 16 + g;
#pragma unroll
            for (int tn = 0; tn < 8; tn++) {
                int col = wn * 64 + tn * 8 + t2;
                int gc  = nt * 128 + col;
                float ee0 = ee_s[gc], ee1 = ee_s[gc + 1];
                float d00 = zzr[tm*2+0] + ee0 - 2.f * acc[tm][tn][0];
                float d01 = zzr[tm*2+0] + ee1 - 2.f * acc[tm][tn][1];
                float d10 = zzr[tm*2+1] + ee0 - 2.f * acc[tm][tn][2];
                float d11 = zzr[tm*2+1] + ee1 - 2.f * acc[tm][tn][3];

                int s0 = tm * 2, s1 = tm * 2 + 1;
                if (d00 < osm_m[s0]) { osm_s[s0] = osm_s[s0] * ex2((d00 - osm_m[s0]) * C) + 1.f; osm_m[s0] = d00; osm_i[s0] = gc; }
                else osm_s[s0] += ex2((osm_m[s0] - d00) * C);
                if (d01 < osm_m[s0]) { osm_s[s0] = osm_s[s0] * ex2((d01 - osm_m[s0]) * C) + 1.f; osm_m[s0] = d01; osm_i[s0] = gc + 1; }
                else osm_s[s0] += ex2((osm_m[s0] - d01) * C);
                if (d10 < osm_m[s1]) { osm_s[s1] = osm_s[s1] * ex2((d10 - osm_m[s1]) * C) + 1.f; osm_m[s1] = d10; osm_i[s1] = gc; }
                else osm_s[s1] += ex2((osm_m[s1] - d10) * C);
                if (d11 < osm_m[s1]) { osm_s[s1] = osm_s[s1] * ex2((d11 - osm_m[s1]) * C) + 1.f; osm_m[s1] = d11; osm_i[s1] = gc + 1; }
                else osm_s[s1] += ex2((osm_m[s1] - d11) * C);

                float* p0 = out + OFF_SA + (size_t)(brow + r_lo) * K_CODES + gc;
                float* p1 = out + OFF_SA + (size_t)(brow + r_lo + 8) * K_CODES + gc;
                p0[0] = d00; p0[1] = d01;
                p1[0] = d10; p1[1] = d11;
            }
        }
    }

    // ---- merge online states: lanes (xor 1,2) then across the two warp-halves
#pragma unroll
    for (int sl = 0; sl < 4; sl++) {
        float m = osm_m[sl], s = osm_s[sl]; int i = osm_i[sl];
#pragma unroll
        for (int off = 1; off <= 2; off <<= 1) {
            float om = __shfl_xor_sync(0xffffffffu, m, off);
            float os = __shfl_xor_sync(0xffffffffu, s, off);
            int   oi = __shfl_xor_sync(0xffffffffu, i, off);
            osm_merge(m, s, i, om, os, oi, C);
        }
        if ((lane & 3) == 0) {
            int row = wm * 32 + (sl >> 1) * 16 + g + (sl & 1) * 8;
            pm[row * 2 + wn] = m; ps[row * 2 + wn] = s; pi[row * 2 + wn] = i;
        }
    }
    __syncthreads();
    if (tid < 128) {
        float m = pm[tid * 2], s = ps[tid * 2]; int i = pi[tid * 2];
        osm_merge(m, s, i, pm[tid * 2 + 1], ps[tid * 2 + 1], pi[tid * 2 + 1], C);
        fm[tid] = m; fs[tid] = s; fi[tid] = i;
    }
    __syncthreads();

    // ---- Phase B: single-pass softmax normalize + z_q + commitment + segsums
    float commit_acc = 0.f;
    for (int rr = 0; rr < 16; rr++) {
        int row = w * 16 + rr;
        float dmin = fm[row];
        float invs = 1.0f / fs[row];
        int   code = fi[row];
        int grow = brow + row;

        float* sarow = out + OFF_SA + (size_t)grow * K_CODES;
#pragma unroll 4
        for (int it = 0; it < 32; it++) {
            int i = lane + it * 32;
            float d = sarow[i];
            sarow[i] = ex2((dmin - d) * C) * invs;
        }

        const float* erow = embed + (size_t)code * D_DIM;
        const float* zrow = z + (size_t)grow * D_DIM;
        float* zqrow = out + OFF_ZQ + (size_t)grow * D_DIM;
        float* esrow = g_esum + (size_t)code * D_DIM;
#pragma unroll
        for (int it = 0; it < 8; it++) {
            int d = lane + it * 32;
            float ev = erow[d];
            float zv = zrow[d];
            zqrow[d] = ev;
            float df = zv - ev;
            commit_acc += df * df;
            atomicAdd(&esrow[d], zv);
        }
        if (lane == 0) {
            atomicAdd(&g_counts[code], 1.0f);
            out[OFF_CODES + grow] = (float)code;
        }
    }
#pragma unroll
    for (int o = 16; o; o >>= 1) commit_acc += __shfl_xor_sync(0xffffffffu, commit_acc, o);
    if (lane == 0) red[w] = commit_acc;
    __syncthreads();
    if (tid == 0) {
        float t = 0.f;
        for (int i = 0; i < 8; i++) t += red[i];
        atomicAdd(&g_commit, t);
    }
}

// ---------------------------------------------------------------------------
__global__ void __launch_bounds__(1024) ema_kernel(const float* __restrict__ cs,
                                                   float* __restrict__ out) {
    __shared__ float sh[33];
    int t = threadIdx.x, lane = t & 31, wid = t >> 5;

    float cnt = g_counts[t];
    float ncs = 0.99f * cs[t] + 0.01f * cnt;
    out[OFF_CS + t] = ncs;

    float v = ncs;
#pragma unroll
    for (int o = 16; o; o >>= 1) v += __shfl_xor_sync(0xffffffffu, v, o);
    if (lane == 0) sh[wid] = v;
    __syncthreads();
    if (t < 32) {
        float r = sh[t];
#pragma unroll
        for (int o = 16; o; o >>= 1) r += __shfl_xor_sync(0xffffffffu, r, o);
        if (t == 0) sh[32] = r;
    }
    __syncthreads();
    float n = sh[32];
    __syncthreads();

    float avg = cnt * (1.0f / (float)N_TOK);
    float term = -avg * logf(avg + 1e-10f);
    v = term;
#pragma unroll
    for (int o = 16; o; o >>= 1) v += __shfl_xor_sync(0xffffffffu, v, o);
    if (lane == 0) sh[wid] = v;
    __syncthreads();
    if (t < 32) {
        float r = sh[t];
#pragma unroll
        for (int o = 16; o; o >>= 1) r += __shfl_xor_sync(0xffffffffu, r, o);
        if (t == 0) {
            out[OFF_ENT]  = r;
            out[OFF_PERP] = expf(r);
            out[OFF_LOSS] = g_commit * (1.0f / 8388608.0f);
        }
    }
    float csn = (ncs + 1e-5f) / (n + 1024.0f * 1e-5f) * n;
    g_invcs[t] = 1.0f / csn;
}

__global__ void __launch_bounds__(1024) embed_update_kernel(const float* __restrict__ ea,
                                                            float* __restrict__ out) {
    int i = blockIdx.x * 1024 + threadIdx.x;
    float v = 0.99f * ea[i] + 0.01f * g_esum[i];
    out[OFF_EA + i] = v;
    out[OFF_EMBED + i] = v * g_invcs[i >> 8];
}

// ---------------------------------------------------------------------------
extern "C" void kernel_launch(void* const* d_in, const int* in_sizes, int n_in,
                              void* d_out, int out_size) {
    const float* z     = (const float*)d_in[0];
    const float* embed = (const float*)d_in[1];
    const float* cs    = (const float*)d_in[2];
    const float* ea    = (const float*)d_in[3];
    float* out = (float*)d_out;

    cudaFuncSetAttribute(dist_kernel, cudaFuncAttributeMaxDynamicSharedMemorySize, SMEM_BYTES);

    init_zero_kernel<<<258, 1024>>>();
    embed_prep_kernel<<<128, 256>>>(embed);
    dist_kernel<<<N_TOK / 128, 256, SMEM_BYTES>>>(z, embed, out);
    ema_kernel<<<1, 1024>>>(cs, out);
    embed_update_kernel<<<256, 1024>>>(ea, out);
    (void)in_sizes; (void)n_in; (void)out_size;
}

// round 12
// speedup vs baseline: 3.4452x; 1.1686x over previous
#include <cuda_runtime.h>
#include <cuda_bf16.h>
#include <cstdint>

#define N_TOK   32768
#define K_CODES 1024
#define D_DIM   256
#define BM      64

// Output layout: reference tuple concatenated as float32 in return order.
#define OFF_ZQ    0ull
#define OFF_CODES 8388608ull
#define OFF_LOSS  8421376ull
#define OFF_PERP  8421377ull
#define OFF_ENT   8421378ull
#define OFF_SA    8421379ull
#define OFF_EMBED 41975811ull
#define OFF_CS    42237955ull
#define OFF_EA    42238979ull

// ---------------------------------------------------------------------------
// Scratch (__device__ globals; no runtime allocation allowed)
__device__ float g_esum[K_CODES * D_DIM];
__device__ float g_counts[K_CODES];
__device__ float g_commit;
__device__ float g_ee[K_CODES];
__device__ float g_invcs[K_CODES];
__device__ __align__(16) unsigned short g_eh[K_CODES * D_DIM];  // embed bf16 hi
__device__ __align__(16) unsigned short g_el[K_CODES * D_DIM];  // embed bf16 lo

// ---------------------------------------------------------------------------
__device__ __forceinline__ uint32_t smem_u32(const void* p) {
    uint32_t a;
    asm("{ .reg .u64 t; cvta.to.shared.u64 t, %1; cvt.u32.u64 %0, t; }" : "=r"(a) : "l"(p));
    return a;
}
__device__ __forceinline__ float ex2(float x) {
    float r; asm("ex2.approx.ftz.f32 %0, %1;" : "=f"(r) : "f"(x)); return r;
}
#define SWZ(o) ((o) ^ (((o) >> 3) & 0x70u))

#define LDSM4(r, a) \
    asm volatile("ldmatrix.sync.aligned.m8n8.x4.shared.b16 {%0,%1,%2,%3}, [%4];" \
        : "=r"((r)[0]), "=r"((r)[1]), "=r"((r)[2]), "=r"((r)[3]) : "r"(a))
#define MMA16816(d, a, b) \
    asm volatile("mma.sync.aligned.m16n8k16.row.col.f32.bf16.bf16.f32 " \
        "{%0,%1,%2,%3},{%4,%5,%6,%7},{%8,%9},{%0,%1,%2,%3};" \
        : "+f"((d)[0]), "+f"((d)[1]), "+f"((d)[2]), "+f"((d)[3]) \
        : "r"((a)[0]), "r"((a)[1]), "r"((a)[2]), "r"((a)[3]), "r"((b)[0]), "r"((b)[1]))

#define CP_ASYNC16(saddr, gptr) \
    asm volatile("cp.async.cg.shared.global [%0], [%1], 16;" :: "r"(saddr), "l"(gptr))
#define CP_COMMIT() asm volatile("cp.async.commit_group;" ::: "memory")
#define CP_WAIT(n)  asm volatile("cp.async.wait_group %0;" :: "n"(n) : "memory")

__device__ __forceinline__ unsigned short f2bf(float v) {
    __nv_bfloat16 b = __float2bfloat16(v);
    return *reinterpret_cast<unsigned short*>(&b);
}
__device__ __forceinline__ float bf2f(unsigned short u) {
    __nv_bfloat16 b = *reinterpret_cast<__nv_bfloat16*>(&u);
    return __bfloat162float(b);
}

// ---------------------------------------------------------------------------
// embed prep: zero scratch + bf16 hi/lo split + squared norms. One warp/code.
__global__ void __launch_bounds__(256) embed_prep_kernel(const float* __restrict__ embed) {
    int gid = blockIdx.x * 256 + threadIdx.x;   // 0..32767
    // zero g_esum (262144), g_counts (1024), g_commit
#pragma unroll
    for (int k = 0; k < 8; k++) g_esum[gid + k * 32768] = 0.f;
    if (gid < K_CODES) g_counts[gid] = 0.f;
    if (gid == 0) g_commit = 0.f;

    int w = threadIdx.x >> 5, lane = threadIdx.x & 31;
    int k = blockIdx.x * 8 + w;
    const float* e = embed + (size_t)k * D_DIM;
    float s = 0.f;
#pragma unroll
    for (int j = 0; j < 8; j++) {
        int d = lane + 32 * j;
        float v = e[d];
        unsigned short h = f2bf(v);
        unsigned short l = f2bf(v - bf2f(h));
        g_eh[k * D_DIM + d] = h;
        g_el[k * D_DIM + d] = l;
        s += v * v;
    }
#pragma unroll
    for (int o = 16; o; o >>= 1) s += __shfl_xor_sync(0xffffffffu, s, o);
    if (lane == 0) g_ee[k] = s;
}

// ---------------------------------------------------------------------------
// SMEM layout (bytes) — total 105088 -> 2 CTAs/SM
#define SM_RED  0u       // 8 floats
#define SM_ZZ   64u      // 64 floats -> ends 320
#define SM_PM   320u     // 128 floats -> 832
#define SM_PS   832u     // 128 floats -> 1344
#define SM_PI   1344u    // 128 ints  -> 1856
#define SM_FM   1856u    // 64 floats -> 2112
#define SM_FS   2112u    // 64 floats -> 2368
#define SM_FI   2368u    // 64 ints   -> 2624
#define SM_EE   2624u    // 1024 floats -> 6720
#define SM_Z    6784u    // 8 subtiles (hi c0..3, lo c0..3) x 8192 = 65536 -> 72320
#define SM_E    72320u   // 2 buffers x (hi 8192 + lo 8192) = 32768 -> 105088
#define SMEM_BYTES 105088u

// merge two online-softmax states
__device__ __forceinline__ void osm_merge(float& m, float& s, int& i,
                                          float om, float os, int oi, float C) {
    if (om < m || (om == m && oi < i)) {
        s = os + s * ex2((om - m) * C);
        m = om; i = oi;
    } else {
        s = s + os * ex2((m - om) * C);
    }
}

// async copy of E chunk L (nt = L>>2, c = L&3): 64 codes x 64 d, hi+lo = 16 KB
__device__ __forceinline__ void copy_chunk(uint32_t sb, int L, int tid) {
    int nt = L >> 2, c = L & 3;
    uint32_t dstb = SM_E + (uint32_t)(L & 1) * 16384u;
#pragma unroll
    for (int m = 0; m < 4; m++) {
        int linear = m * 256 + tid;          // 0..1023
        int s = linear >> 9, rem = linear & 511;
        int i = rem >> 3, grp = rem & 7;
        const unsigned short* src = s ? g_el : g_eh;
        const void* gp = (const void*)(src + ((size_t)(nt * 64 + i) * D_DIM + c * 64 + grp * 8));
        uint32_t off = SWZ((uint32_t)(i * 128 + grp * 16));
        CP_ASYNC16(sb + dstb + (uint32_t)s * 8192u + off, gp);
    }
}

__global__ void __launch_bounds__(256, 2) dist_kernel(
    const float* __restrict__ z, const float* __restrict__ embed,
    float* __restrict__ out)
{
    extern __shared__ char smem[];
    const uint32_t sb = smem_u32(smem);
    const int tid = threadIdx.x;
    const int w = tid >> 5, lane = tid & 31;
    const int wm = w & 3, wn = w >> 2;        // warp grid 4 (M) x 2 (N)
    const int brow = blockIdx.x * BM;
    const float C = 14.4269504088896341f;      // 10 / ln(2)

    float* red  = (float*)(smem + SM_RED);
    float* zz   = (float*)(smem + SM_ZZ);
    float* ee_s = (float*)(smem + SM_EE);
    float* pm   = (float*)(smem + SM_PM);
    float* ps   = (float*)(smem + SM_PS);
    int*   pi   = (int*)  (smem + SM_PI);
    float* fm   = (float*)(smem + SM_FM);
    float* fs   = (float*)(smem + SM_FS);
    int*   fi   = (int*)  (smem + SM_FI);

    if (tid < BM) zz[tid] = 0.f;
    __syncthreads();

    // kick off E chunk 0 fetch; overlaps z-tile load/split
    copy_chunk(sb, 0, tid);
    CP_COMMIT();

    // ---- load z tile [64 x 256] -> bf16 hi/lo split, swizzled smem, row norms
    {
        int r = tid >> 2, q = tid & 3;       // 4 threads per row, 64 d each
        float s = 0.f;
#pragma unroll
        for (int j = 0; j < 8; j++) {
            int d = q * 64 + j * 8;
            const float4* zp = (const float4*)(z + (size_t)(brow + r) * D_DIM + d);
            float4 a = zp[0], b = zp[1];
            float f[8] = {a.x, a.y, a.z, a.w, b.x, b.y, b.z, b.w};
            uint32_t hv[4], lv[4];
#pragma unroll
            for (int p = 0; p < 4; p++) {
                unsigned short h0 = f2bf(f[2*p]),   h1 = f2bf(f[2*p+1]);
                unsigned short l0 = f2bf(f[2*p]   - bf2f(h0));
                unsigned short l1 = f2bf(f[2*p+1] - bf2f(h1));
                hv[p] = (uint32_t)h0 | ((uint32_t)h1 << 16);
                lv[p] = (uint32_t)l0 | ((uint32_t)l1 << 16);
                s += f[2*p]*f[2*p] + f[2*p+1]*f[2*p+1];
            }
            int col = j * 8;                  // within the q-th 64-d chunk
            uint32_t off = SWZ((uint32_t)(r * 128 + col * 2));
            *(uint4*)(smem + SM_Z + (0 + q) * 8192 + off) = make_uint4(hv[0],hv[1],hv[2],hv[3]);
            *(uint4*)(smem + SM_Z + (4 + q) * 8192 + off) = make_uint4(lv[0],lv[1],lv[2],lv[3]);
        }
        atomicAdd(&zz[r], s);
    }
    // preload ALL code norms once (1024 floats)
#pragma unroll
    for (int k = 0; k < 4; k++) ee_s[tid + k * 256] = g_ee[tid + k * 256];
    __syncthreads();

    const int g  = lane >> 2;           // fragment row-in-8
    const int t2 = (lane & 3) * 2;      // fragment col pair
    float zzr[2];
    zzr[0] = zz[wm * 16 + g];
    zzr[1] = zz[wm * 16 + g + 8];

    // online softmax state per owned row-slot (rows wm*16+g, +8)
    float osm_m[2] = {3.4e38f, 3.4e38f};
    float osm_s[2] = {0.f, 0.f};
    int   osm_i[2] = {0, 0};

    for (int nt = 0; nt < 16; nt++) {
        float acc[4][4];
#pragma unroll
        for (int tn = 0; tn < 4; tn++)
#pragma unroll
            for (int q = 0; q < 4; q++) acc[tn][q] = 0.f;

        for (int c = 0; c < 4; c++) {
            const int L = nt * 4 + c;
            if (L + 1 < 64) {
                copy_chunk(sb, L + 1, tid);
                CP_COMMIT();
                CP_WAIT(1);          // chunk L complete, L+1 in flight
            } else {
                CP_WAIT(0);
            }
            __syncthreads();

            const uint32_t eb = SM_E + (uint32_t)(L & 1) * 16384u;
#pragma unroll
            for (int ks = 0; ks < 4; ks++) {
                // A fragments (hi + lo), one 16-row tile
                uint32_t ah[4], al[4];
                {
                    int row = wm * 16 + (lane & 15);
                    uint32_t kg = (uint32_t)(ks * 2 + (lane >> 4));
                    uint32_t boff = (uint32_t)(row * 128) + ((kg ^ (row & 7)) << 4);
                    LDSM4(ah, sb + SM_Z + (0 + c) * 8192 + boff);
                    LDSM4(al, sb + SM_Z + (4 + c) * 8192 + boff);
                }
                // B fragments via x4: 4 matrices = (j-pair) x (k-group)
                uint32_t bh[4][2], bl[4][2];
#pragma unroll
                for (int jp = 0; jp < 2; jp++) {
                    int mi = lane >> 3;                   // matrix index 0..3
                    int row = wn * 32 + (jp * 2 + (mi >> 1)) * 8 + (lane & 7);
                    uint32_t kg = (uint32_t)(ks * 2 + (mi & 1));
                    uint32_t boff = (uint32_t)(row * 128) + ((kg ^ (row & 7)) << 4);
                    uint32_t q[4];
                    LDSM4(q, sb + eb + boff);
                    bh[jp*2+0][0] = q[0]; bh[jp*2+0][1] = q[1];
                    bh[jp*2+1][0] = q[2]; bh[jp*2+1][1] = q[3];
                    LDSM4(q, sb + eb + 8192u + boff);
                    bl[jp*2+0][0] = q[0]; bl[jp*2+0][1] = q[1];
                    bl[jp*2+1][0] = q[2]; bl[jp*2+1][1] = q[3];
                }
                // hh, then hl, then lh
#pragma unroll
                for (int j = 0; j < 4; j++) MMA16816(acc[j], ah, bh[j]);
#pragma unroll
                for (int j = 0; j < 4; j++) MMA16816(acc[j], ah, bl[j]);
#pragma unroll
                for (int j = 0; j < 4; j++) MMA16816(acc[j], al, bh[j]);
            }
            __syncthreads();   // all warps done with buffer (L&1) before refill
        }

        // ---- epilogue: dist, online softmax, scalar STG to soft_assign slot
        // (OFF_SA is an ODD float offset -> rows only 4B-aligned)
        int r0 = wm * 16 + g;
#pragma unroll
        for (int tn = 0; tn < 4; tn++) {
            int col = wn * 32 + tn * 8 + t2;
            int gc  = nt * 64 + col;
            float ee0 = ee_s[gc], ee1 = ee_s[gc + 1];
            float d00 = zzr[0] + ee0 - 2.f * acc[tn][0];
            float d01 = zzr[0] + ee1 - 2.f * acc[tn][1];
            float d10 = zzr[1] + ee0 - 2.f * acc[tn][2];
            float d11 = zzr[1] + ee1 - 2.f * acc[tn][3];

            if (d00 < osm_m[0]) { osm_s[0] = osm_s[0] * ex2((d00 - osm_m[0]) * C) + 1.f; osm_m[0] = d00; osm_i[0] = gc; }
            else osm_s[0] += ex2((osm_m[0] - d00) * C);
            if (d01 < osm_m[0]) { osm_s[0] = osm_s[0] * ex2((d01 - osm_m[0]) * C) + 1.f; osm_m[0] = d01; osm_i[0] = gc + 1; }
            else osm_s[0] += ex2((osm_m[0] - d01) * C);
            if (d10 < osm_m[1]) { osm_s[1] = osm_s[1] * ex2((d10 - osm_m[1]) * C) + 1.f; osm_m[1] = d10; osm_i[1] = gc; }
            else osm_s[1] += ex2((osm_m[1] - d10) * C);
            if (d11 < osm_m[1]) { osm_s[1] = osm_s[1] * ex2((d11 - osm_m[1]) * C) + 1.f; osm_m[1] = d11; osm_i[1] = gc + 1; }
            else osm_s[1] += ex2((osm_m[1] - d11) * C);

            float* p0 = out + OFF_SA + (size_t)(brow + r0) * K_CODES + gc;
            float* p1 = out + OFF_SA + (size_t)(brow + r0 + 8) * K_CODES + gc;
            p0[0] = d00; p0[1] = d01;
            p1[0] = d10; p1[1] = d11;
        }
    }

    // ---- merge online states: lanes (xor 1,2) then across the two warp-halves
#pragma unroll
    for (int sl = 0; sl < 2; sl++) {
        float m = osm_m[sl], s = osm_s[sl]; int i = osm_i[sl];
#pragma unroll
        for (int off = 1; off <= 2; off <<= 1) {
            float om = __shfl_xor_sync(0xffffffffu, m, off);
            float os = __shfl_xor_sync(0xffffffffu, s, off);
            int   oi = __shfl_xor_sync(0xffffffffu, i, off);
            osm_merge(m, s, i, om, os, oi, C);
        }
        if ((lane & 3) == 0) {
            int row = wm * 16 + g + sl * 8;
            pm[row * 2 + wn] = m; ps[row * 2 + wn] = s; pi[row * 2 + wn] = i;
        }
    }
    __syncthreads();
    if (tid < BM) {
        float m = pm[tid * 2], s = ps[tid * 2]; int i = pi[tid * 2];
        osm_merge(m, s, i, pm[tid * 2 + 1], ps[tid * 2 + 1], pi[tid * 2 + 1], C);
        fm[tid] = m; fs[tid] = s; fi[tid] = i;
    }
    __syncthreads();

    // ---- Phase B: single-pass softmax normalize + z_q + commitment + segsums
    float commit_acc = 0.f;
    for (int rr = 0; rr < 8; rr++) {
        int row = w * 8 + rr;
        float dmin = fm[row];
        float invs = 1.0f / fs[row];
        int   code = fi[row];
        int grow = brow + row;

        float* sarow = out + OFF_SA + (size_t)grow * K_CODES;
#pragma unroll 4
        for (int it = 0; it < 32; it++) {
            int i = lane + it * 32;
            float d = sarow[i];
            sarow[i] = ex2((dmin - d) * C) * invs;
        }

        const float* erow = embed + (size_t)code * D_DIM;
        const float* zrow = z + (size_t)grow * D_DIM;
        float* zqrow = out + OFF_ZQ + (size_t)grow * D_DIM;
        float* esrow = g_esum + (size_t)code * D_DIM;
#pragma unroll
        for (int it = 0; it < 8; it++) {
            int d = lane + it * 32;
            float ev = erow[d];
            float zv = zrow[d];
            zqrow[d] = ev;
            float df = zv - ev;
            commit_acc += df * df;
            atomicAdd(&esrow[d], zv);
        }
        if (lane == 0) {
            atomicAdd(&g_counts[code], 1.0f);
            out[OFF_CODES + grow] = (float)code;
        }
    }
#pragma unroll
    for (int o = 16; o; o >>= 1) commit_acc += __shfl_xor_sync(0xffffffffu, commit_acc, o);
    if (lane == 0) red[w] = commit_acc;
    __syncthreads();
    if (tid == 0) {
        float t = 0.f;
        for (int i = 0; i < 8; i++) t += red[i];
        atomicAdd(&g_commit, t);
    }
}

// ---------------------------------------------------------------------------
__global__ void __launch_bounds__(1024) ema_kernel(const float* __restrict__ cs,
                                                   float* __restrict__ out) {
    __shared__ float sh[33];
    int t = threadIdx.x, lane = t & 31, wid = t >> 5;

    float cnt = g_counts[t];
    float ncs = 0.99f * cs[t] + 0.01f * cnt;
    out[OFF_CS + t] = ncs;

    float v = ncs;
#pragma unroll
    for (int o = 16; o; o >>= 1) v += __shfl_xor_sync(0xffffffffu, v, o);
    if (lane == 0) sh[wid] = v;
    __syncthreads();
    if (t < 32) {
        float r = sh[t];
#pragma unroll
        for (int o = 16; o; o >>= 1) r += __shfl_xor_sync(0xffffffffu, r, o);
        if (t == 0) sh[32] = r;
    }
    __syncthreads();
    float n = sh[32];
    __syncthreads();

    float avg = cnt * (1.0f / (float)N_TOK);
    float term = -avg * logf(avg + 1e-10f);
    v = term;
#pragma unroll
    for (int o = 16; o; o >>= 1) v += __shfl_xor_sync(0xffffffffu, v, o);
    if (lane == 0) sh[wid] = v;
    __syncthreads();
    if (t < 32) {
        float r = sh[t];
#pragma unroll
        for (int o = 16; o; o >>= 1) r += __shfl_xor_sync(0xffffffffu, r, o);
        if (t == 0) {
            out[OFF_ENT]  = r;
            out[OFF_PERP] = expf(r);
            out[OFF_LOSS] = g_commit * (1.0f / 8388608.0f);
        }
    }
    float csn = (ncs + 1e-5f) / (n + 1024.0f * 1e-5f) * n;
    g_invcs[t] = 1.0f / csn;
}

__global__ void __launch_bounds__(1024) embed_update_kernel(const float* __restrict__ ea,
                                                            float* __restrict__ out) {
    int i = blockIdx.x * 1024 + threadIdx.x;
    float v = 0.99f * ea[i] + 0.01f * g_esum[i];
    out[OFF_EA + i] = v;
    out[OFF_EMBED + i] = v * g_invcs[i >> 8];
}

// ---------------------------------------------------------------------------
extern "C" void kernel_launch(void* const* d_in, const int* in_sizes, int n_in,
                              void* d_out, int out_size) {
    const float* z     = (const float*)d_in[0];
    const float* embed = (const float*)d_in[1];
    const float* cs    = (const float*)d_in[2];
    const float* ea    = (const float*)d_in[3];
    float* out = (float*)d_out;

    cudaFuncSetAttribute(dist_kernel, cudaFuncAttributeMaxDynamicSharedMemorySize, SMEM_BYTES);

    embed_prep_kernel<<<128, 256>>>(embed);
    dist_kernel<<<N_TOK / BM, 256, SMEM_BYTES>>>(z, embed, out);
    ema_kernel<<<1, 1024>>>(cs, out);
    embed_update_kernel<<<256, 1024>>>(ea, out);
    (void)in_sizes; (void)n_in; (void)out_size;
}